// round 15
// baseline (speedup 1.0000x reference)
#include <cuda_runtime.h>
#include <cuda_fp16.h>
#include <cstdint>

// ---------------------------------------------------------------------------
// out = emb[ids_en] + S @ V,  vocab collapse:
//   proj = emb @ Qdense [300,512] -> fp32 g_proj + fp16 g_pf16
//   G = proj projT -> packed fp16 {hi|lo} g_grams (stride 304, col 0 zeroed)
//   sbuild (per batch x 2 CTAs): gather 32 G rows coalesced, column-select ->
//     S hi/lo fp16 planes in global g_sp (L2-resident)
//   main (per batch x 4 column-CTAs, 128 thr, 4 CTAs/SM): enc = S @ V via
//     fp16 2-product mma  D = (S_hi + S_lo) * V_hi  (32q x 64n warp tiles).
//     EPILOGUE v2: fragments -> smem fp32 enc buffer (reusing dead S/V plane
//     region) -> fully coalesced 128B-line  out = enc + emb[ids_en]  pass.
// (tcgen05 unavailable: harness builds through plain compute_103 PTX.)
// ---------------------------------------------------------------------------

namespace {
constexpr int kB = 1024;
constexpr int kV = 300;
constexpr int kVP = 304;      // g_grams row stride (words)
constexpr int kD = 512;
constexpr int kN = 128;       // cols per main CTA (batch split in 4)

// sbuild smem (32 G rows per CTA)
constexpr int GSTRB = 1216;                      // G row bytes (304 words)
constexpr int SB_TFR = 32 * GSTRB;               // 38,912
constexpr int SMEM_SB = SB_TFR + 256;            // 39,168 -> 5 CTAs/SM

// main smem
constexpr int PROW2 = 272;                       // P plane row stride (128 fp16 + 16B)
constexpr int SROWB = 144;                       // S plane row stride (64 fp16 + 16B)
constexpr int OFF_P   = 0;                       // single V_hi plane
constexpr int OFF_SHI = 64 * PROW2;              // 17,408
constexpr int OFF_SLO = OFF_SHI + 64 * SROWB;    // 26,624
constexpr int DSL     = OFF_SLO - OFF_SHI;
constexpr int OFF_TFR = OFF_SLO + 64 * SROWB;    // 35,840
constexpr int OFF_TEN = OFF_TFR + 256;
constexpr int SMEM_MAIN = OFF_TEN + 256;         // 36,352 -> 4 CTAs/SM
// fp32 enc buffer reuses [0, OFF_TFR) after the MMA loop (planes dead then)
constexpr int ESTR = 136;                        // enc row stride (floats)
static_assert(64 * ESTR * 4 <= OFF_TFR, "enc buffer must fit in plane region");
}

__device__ float    g_proj [kV * kD];        // fp32 proj (gram input)
__device__ __half   g_pf16 [kV * kD];        // fp16 proj (main B operand)
__device__ uint32_t g_grams[kV * kVP];       // packed {fp16 hi | fp16 lo}, col 0 = 0
__device__ uint32_t g_sp   [kB * 4096];      // per-batch S planes: [b][2][64][32]

// ---------------- helpers --------------------------------------------------
__device__ __forceinline__ uint32_t smem_u32(const void* p) {
    uint32_t a;
    asm("{ .reg .u64 t; cvta.to.shared.u64 t, %1; cvt.u32.u64 %0, t; }"
        : "=r"(a) : "l"(p));
    return a;
}
__device__ __forceinline__ uint32_t prmt(uint32_t a, uint32_t b, uint32_t sel) {
    uint32_t d;
    asm("prmt.b32 %0, %1, %2, %3;" : "=r"(d) : "r"(a), "r"(b), "r"(sel));
    return d;
}
__device__ __forceinline__ void ldsm4(uint32_t* r, uint32_t addr) {
    asm volatile("ldmatrix.sync.aligned.m8n8.x4.shared.b16 {%0,%1,%2,%3}, [%4];"
                 : "=r"(r[0]), "=r"(r[1]), "=r"(r[2]), "=r"(r[3]) : "r"(addr));
}
__device__ __forceinline__ void ldsm4t(uint32_t* r, uint32_t addr) {
    asm volatile("ldmatrix.sync.aligned.m8n8.x4.trans.shared.b16 {%0,%1,%2,%3}, [%4];"
                 : "=r"(r[0]), "=r"(r[1]), "=r"(r[2]), "=r"(r[3]) : "r"(addr));
}
__device__ __forceinline__ void mma_f16(float* c, const uint32_t* a,
                                        const uint32_t* b) {
    asm volatile(
        "mma.sync.aligned.m16n8k16.row.col.f32.f16.f16.f32 "
        "{%0,%1,%2,%3}, {%4,%5,%6,%7}, {%8,%9}, {%0,%1,%2,%3};"
        : "+f"(c[0]), "+f"(c[1]), "+f"(c[2]), "+f"(c[3])
        : "r"(a[0]), "r"(a[1]), "r"(a[2]), "r"(a[3]), "r"(b[0]), "r"(b[1]));
}
// fp32 -> packed {fp16 hi << 16 | fp16 residual lo}
__device__ __forceinline__ uint32_t pack_split16(float v) {
    __half h = __float2half_rn(v);
    float hf = __half2float(h);
    __half l = __float2half_rn(v - hf);
    return ((uint32_t)__half_as_ushort(h) << 16) | __half_as_ushort(l);
}

// ---------------------------------------------------------------------------
// Kernel 1: proj = emb @ Qdense -> g_proj fp32 + g_pf16. (validated)
// ---------------------------------------------------------------------------
__global__ void __launch_bounds__(256) proj_kernel(const float* __restrict__ emb,
                                                   const float* __restrict__ Wq) {
    __shared__ float As[16 * 65];
    __shared__ float Bs[64 * 36];
    const int r0 = blockIdx.x * 16, c0 = blockIdx.y * 32;
    const int t = threadIdx.x;
    const int r = t & 15, cg = t >> 4;
    float2 acc = make_float2(0.f, 0.f);

    for (int kc = 0; kc < kD; kc += 64) {
        __syncthreads();
        {
            int ar = t >> 4, ak4 = t & 15;
            float4 v = make_float4(0.f, 0.f, 0.f, 0.f);
            if (r0 + ar < kV) v = *(const float4*)(emb + (r0 + ar) * kD + kc + ak4 * 4);
            float* d = As + ar * 65 + ak4 * 4;
            d[0] = v.x; d[1] = v.y; d[2] = v.z; d[3] = v.w;
        }
        {
            int c4 = t & 7;
#pragma unroll
            for (int j = 0; j < 2; j++) {
                int bk = (t >> 3) + 32 * j;
                float4 v = *(const float4*)(Wq + (kc + bk) * kD + c0 + c4 * 4);
                *(float4*)(Bs + bk * 36 + c4 * 4) = v;
            }
        }
        __syncthreads();
#pragma unroll 8
        for (int kk = 0; kk < 64; kk++) {
            float a = As[r * 65 + kk];
            float2 bv = *(const float2*)(Bs + kk * 36 + cg * 2);
            acc.x = fmaf(a, bv.x, acc.x);
            acc.y = fmaf(a, bv.y, acc.y);
        }
    }
    if (r0 + r < kV) {
        int idx = (r0 + r) * kD + c0 + cg * 2;
        *(float2*)(g_proj + idx) = acc;
        *(__half2*)(g_pf16 + idx) = __floats2half2_rn(acc.x, acc.y);
    }
}

// ---------------------------------------------------------------------------
// Kernel 2: G = proj projT -> packed fp16-split g_grams, col 0 zeroed.
// ---------------------------------------------------------------------------
__global__ void __launch_bounds__(256) gram_kernel() {
    __shared__ float As[32 * 130];
    __shared__ float Bs[32 * 130];
    const int i0 = blockIdx.x * 32, j0 = blockIdx.y * 32;
    const int t = threadIdx.x;
    const int tx = t & 15, ty = t >> 4;
    float a00 = 0.f, a01 = 0.f, a10 = 0.f, a11 = 0.f;

    for (int kc = 0; kc < kD; kc += 128) {
        __syncthreads();
        {
            int sr = t >> 3;
#pragma unroll
            for (int j = 0; j < 4; j++) {
                int c4 = (t & 7) + 8 * j;
                float4 va = make_float4(0.f, 0.f, 0.f, 0.f);
                float4 vb = make_float4(0.f, 0.f, 0.f, 0.f);
                if (i0 + sr < kV) va = *(const float4*)(g_proj + (i0 + sr) * kD + kc + c4 * 4);
                if (j0 + sr < kV) vb = *(const float4*)(g_proj + (j0 + sr) * kD + kc + c4 * 4);
                float2* da = (float2*)(As + sr * 130 + c4 * 4);
                float2* db = (float2*)(Bs + sr * 130 + c4 * 4);
                da[0] = make_float2(va.x, va.y); da[1] = make_float2(va.z, va.w);
                db[0] = make_float2(vb.x, vb.y); db[1] = make_float2(vb.z, vb.w);
            }
        }
        __syncthreads();
#pragma unroll 8
        for (int kk = 0; kk < 128; kk += 2) {
            float2 x0 = *(const float2*)(As + ty * 130 + kk);
            float2 x1 = *(const float2*)(As + (ty + 16) * 130 + kk);
            float2 y0 = *(const float2*)(Bs + tx * 130 + kk);
            float2 y1 = *(const float2*)(Bs + (tx + 16) * 130 + kk);
            a00 = fmaf(x0.x, y0.x, a00); a00 = fmaf(x0.y, y0.y, a00);
            a01 = fmaf(x0.x, y1.x, a01); a01 = fmaf(x0.y, y1.y, a01);
            a10 = fmaf(x1.x, y0.x, a10); a10 = fmaf(x1.y, y0.y, a10);
            a11 = fmaf(x1.x, y1.x, a11); a11 = fmaf(x1.y, y1.y, a11);
        }
    }
    int i = i0 + ty, j = j0 + tx;
    if (i < kV) {
        if (j < kV)      g_grams[i * kVP + j]      = j ? pack_split16(a00) : 0u;
        if (j + 16 < kV) g_grams[i * kVP + j + 16] = pack_split16(a01);
    }
    if (i + 16 < kV) {
        if (j < kV)      g_grams[(i + 16) * kVP + j]      = j ? pack_split16(a10) : 0u;
        if (j + 16 < kV) g_grams[(i + 16) * kVP + j + 16] = pack_split16(a11);
    }
}

// ---------------------------------------------------------------------------
// Kernel 3 (sbuild): grid (1024, 2); CTA = (batch, 32-q-row half).
// ---------------------------------------------------------------------------
__global__ void __launch_bounds__(256) sbuild_kernel(const int* __restrict__ ids_fr) {
    extern __shared__ char smem[];
    int* tfr = (int*)(smem + SB_TFR);
    const int b = blockIdx.x;
    const int h = blockIdx.y;
    const int tid = threadIdx.x;

    if (tid < 64) tfr[tid] = ids_fr[b * 64 + tid];
    __syncthreads();

    for (int idx = tid; idx < 32 * 76; idx += 256) {
        int r = idx / 76, c = idx - r * 76;
        ((uint4*)(smem + r * GSTRB))[c] =
            __ldg((const uint4*)(g_grams + (size_t)tfr[32 * h + r] * kVP) + c);
    }
    __syncthreads();

    uint32_t* sp = g_sp + ((size_t)b << 12);
    for (int t4 = tid; t4 < 1024; t4 += 256) {
        int i = t4 >> 5, kp = t4 & 31;
        int q = 32 * h + i;
        const uint32_t* grow = (const uint32_t*)(smem + i * GSTRB);
        uint32_t v0 = grow[tfr[2 * kp]];
        uint32_t v1 = grow[tfr[2 * kp + 1]];
        sp[(q << 5) + kp]        = prmt(v0, v1, 0x7632);   // hi plane
        sp[2048 + (q << 5) + kp] = prmt(v0, v1, 0x5410);   // lo plane
    }
}

// ---------------------------------------------------------------------------
// Kernel 4 (main): grid (1024, 4); CTA = (batch, 128-col quarter), 128 thr,
// 36.4 KB smem, 4 CTAs/SM. Warp tile 32q x 64n. Epilogue via smem enc
// buffer -> fully coalesced out stores.
// ---------------------------------------------------------------------------
__global__ void __launch_bounds__(128, 4) main_kernel(
    const int* __restrict__ ids_en, const int* __restrict__ ids_fr,
    const float* __restrict__ emb, float* __restrict__ out) {
    extern __shared__ char smem[];
    const uint32_t sb = smem_u32(smem);
    int* tfr = (int*)(smem + OFF_TFR);
    int* ten = (int*)(smem + OFF_TEN);
    float* enc = (float*)smem;                   // aliases planes after MMA

    const int b = blockIdx.x;
    const int coff = blockIdx.y * kN;
    const int tid = threadIdx.x;
    const int lane = tid & 31, w = tid >> 5;

    if (tid < 64) {
        tfr[tid] = ids_fr[b * 64 + tid];
        ten[tid] = ids_en[b * 64 + tid];
    }
    __syncthreads();

    // ---- Load S planes (coalesced uint4): 1024 tasks, 8 per thread ----------
    {
        const uint4* sp = (const uint4*)(g_sp + ((size_t)b << 12));
#pragma unroll
        for (int i = 0; i < 8; i++) {
            int idx = tid + 128 * i;
            uint4 v = __ldg(sp + idx);
            int w4 = idx * 4;
            int p = w4 >> 11, rem = w4 & 2047;
            int q = rem >> 5, k0 = rem & 31;
            *(uint4*)(smem + (p ? OFF_SLO : OFF_SHI) + q * SROWB + k0 * 4) = v;
        }
    }
    // ---- Stage V_hi plane (64 x 128 fp16): straight copy, 1024 uint4 --------
#pragma unroll
    for (int i = 0; i < 8; i++) {
        int idx = tid + 128 * i;
        int r = idx >> 4, g = idx & 15;
        uint4 v = __ldg((const uint4*)(g_pf16 + (size_t)tfr[r] * kD + coff) + g);
        *(uint4*)(smem + OFF_P + r * PROW2 + g * 16) = v;
    }
    __syncthreads();

    // ---- MMA: warp tile 32q x 64n (warps: mw = w&1, nw = w>>1) -------------
    const int mw = w & 1, nw = w >> 1;
    const uint32_t aS = sb + OFF_SHI
        + (uint32_t)(32 * mw + (lane & 15)) * SROWB + ((lane >> 4) * 16);
    const uint32_t bT = sb + OFF_P + (uint32_t)(lane & 15) * PROW2
        + (uint32_t)(64 * nw + (lane >> 4) * 8) * 2;

    float acc[2][8][4];
#pragma unroll
    for (int m = 0; m < 2; m++)
#pragma unroll
        for (int nt = 0; nt < 8; nt++)
#pragma unroll
            for (int i = 0; i < 4; i++) acc[m][nt][i] = 0.f;

#pragma unroll
    for (int ks = 0; ks < 4; ks++) {
        uint32_t AH0[4], AH1[4], AL0[4], AL1[4];
        ldsm4(AH0, aS + ks * 32);
        ldsm4(AH1, aS + 16 * SROWB + ks * 32);
        ldsm4(AL0, aS + DSL + ks * 32);
        ldsm4(AL1, aS + DSL + 16 * SROWB + ks * 32);
        uint32_t adr = bT + (uint32_t)(ks * 16) * PROW2;
#pragma unroll
        for (int j = 0; j < 2; j++) {
            uint32_t bH0[4], bH1[4];
            ldsm4t(bH0, adr + j * 64);
            ldsm4t(bH1, adr + j * 64 + 32);
            float* a0 = acc[0][4 * j];
            float* a1 = acc[1][4 * j];
            mma_f16(a0,      AH0, bH0);     mma_f16(a0,      AL0, bH0);
            mma_f16(a0 + 4,  AH0, bH0 + 2); mma_f16(a0 + 4,  AL0, bH0 + 2);
            mma_f16(a0 + 8,  AH0, bH1);     mma_f16(a0 + 8,  AL0, bH1);
            mma_f16(a0 + 12, AH0, bH1 + 2); mma_f16(a0 + 12, AL0, bH1 + 2);
            mma_f16(a1,      AH1, bH0);     mma_f16(a1,      AL1, bH0);
            mma_f16(a1 + 4,  AH1, bH0 + 2); mma_f16(a1 + 4,  AL1, bH0 + 2);
            mma_f16(a1 + 8,  AH1, bH1);     mma_f16(a1 + 8,  AL1, bH1);
            mma_f16(a1 + 12, AH1, bH1 + 2); mma_f16(a1 + 12, AL1, bH1 + 2);
        }
    }

    // ---- Epilogue v2: fragments -> smem enc (planes dead), then coalesced ---
    __syncthreads();                              // planes fully consumed
    {
        const int cbs = 64 * nw + 2 * (lane & 3); // col within 128-wide slice
#pragma unroll
        for (int m = 0; m < 2; m++) {
            int ra = 32 * mw + 16 * m + (lane >> 2), rb = ra + 8;
#pragma unroll
            for (int nt = 0; nt < 8; nt++) {
                *(float2*)(enc + ra * ESTR + cbs + nt * 8) =
                    make_float2(acc[m][nt][0], acc[m][nt][1]);
                *(float2*)(enc + rb * ESTR + cbs + nt * 8) =
                    make_float2(acc[m][nt][2], acc[m][nt][3]);
            }
        }
    }
    __syncthreads();
    // coalesced pass: warp-iteration = one full 64-row x 128-col slice row
#pragma unroll
    for (int i = 0; i < 16; i++) {
        int idx = tid + 128 * i;
        int r = idx >> 5, g = idx & 31;           // row, float4 col-group
        float4 v = *(const float4*)(enc + r * ESTR + g * 4);
        float4 e = __ldg((const float4*)(emb + (size_t)ten[r] * kD + coff) + g);
        float4 o = make_float4(v.x + e.x, v.y + e.y, v.z + e.z, v.w + e.w);
        *(float4*)(out + ((size_t)b * 64 + r) * kD + coff + g * 4) = o;
    }
}

// ---------------------------------------------------------------------------
extern "C" void kernel_launch(void* const* d_in, const int* in_sizes, int n_in,
                              void* d_out, int out_size) {
    (void)in_sizes; (void)n_in; (void)out_size;
    const int* ids_en = (const int*)d_in[0];
    const int* ids_fr = (const int*)d_in[1];
    const float* emb  = (const float*)d_in[2];
    const float* Wq   = (const float*)d_in[3];
    float* out        = (float*)d_out;

    proj_kernel<<<dim3(19, 16), 256>>>(emb, Wq);
    gram_kernel<<<dim3(10, 10), 256>>>();
    cudaFuncSetAttribute(sbuild_kernel, cudaFuncAttributeMaxDynamicSharedMemorySize,
                         SMEM_SB);
    sbuild_kernel<<<dim3(kB, 2), 256, SMEM_SB>>>(ids_fr);
    cudaFuncSetAttribute(main_kernel, cudaFuncAttributeMaxDynamicSharedMemorySize,
                         SMEM_MAIN);
    main_kernel<<<dim3(kB, 4), 128, SMEM_MAIN>>>(ids_en, ids_fr, emb, out);
}

// round 16
// speedup vs baseline: 1.4264x; 1.4264x over previous
#include <cuda_runtime.h>
#include <cuda_fp16.h>
#include <cstdint>

// ---------------------------------------------------------------------------
// out = emb[ids_en] + S @ V,  vocab collapse:
//   proj = emb @ Qdense [300,512] -> fp32 g_proj + fp16 g_pf16
//   G = proj projT -> packed fp16 {hi|lo} g_grams (stride 304, col 0 zeroed)
//   sbuild (per batch x 2 CTAs): gather 32 G rows coalesced, column-select ->
//     S hi/lo fp16 planes in global g_sp (L2-resident)
//   main (per batch x 4 column-CTAs, 128 thr, 4 CTAs/SM): enc = S @ V via
//     fp16 2-product mma  D = (S_hi + S_lo) * V_hi  (32q x 64n warp tiles).
//     Staging via cp.async (pure copies; g_sp/g_pf16 are pre-packed planes).
//     Direct epilogue (validated r14): out = enc + emb[ids_en].
// (tcgen05 unavailable: harness builds through plain compute_103 PTX.)
// ---------------------------------------------------------------------------

namespace {
constexpr int kB = 1024;
constexpr int kV = 300;
constexpr int kVP = 304;      // g_grams row stride (words)
constexpr int kD = 512;
constexpr int kN = 128;       // cols per main CTA (batch split in 4)

// sbuild smem (32 G rows per CTA)
constexpr int GSTRB = 1216;                      // G row bytes (304 words)
constexpr int SB_TFR = 32 * GSTRB;               // 38,912
constexpr int SMEM_SB = SB_TFR + 256;            // 39,168 -> 5 CTAs/SM

// main smem
constexpr int PROW2 = 272;                       // P plane row stride (128 fp16 + 16B)
constexpr int SROWB = 144;                       // S plane row stride (64 fp16 + 16B)
constexpr int OFF_P   = 0;                       // single V_hi plane
constexpr int OFF_SHI = 64 * PROW2;              // 17,408
constexpr int OFF_SLO = OFF_SHI + 64 * SROWB;    // 26,624
constexpr int DSL     = OFF_SLO - OFF_SHI;
constexpr int OFF_TFR = OFF_SLO + 64 * SROWB;    // 35,840
constexpr int OFF_TEN = OFF_TFR + 256;
constexpr int SMEM_MAIN = OFF_TEN + 256;         // 36,352 -> 4 CTAs/SM
}

__device__ float    g_proj [kV * kD];        // fp32 proj (gram input)
__device__ __half   g_pf16 [kV * kD];        // fp16 proj (main B operand)
__device__ uint32_t g_grams[kV * kVP];       // packed {fp16 hi | fp16 lo}, col 0 = 0
__device__ uint32_t g_sp   [kB * 4096];      // per-batch S planes: [b][2][64][32]

// ---------------- helpers --------------------------------------------------
__device__ __forceinline__ uint32_t smem_u32(const void* p) {
    uint32_t a;
    asm("{ .reg .u64 t; cvta.to.shared.u64 t, %1; cvt.u32.u64 %0, t; }"
        : "=r"(a) : "l"(p));
    return a;
}
__device__ __forceinline__ uint32_t prmt(uint32_t a, uint32_t b, uint32_t sel) {
    uint32_t d;
    asm("prmt.b32 %0, %1, %2, %3;" : "=r"(d) : "r"(a), "r"(b), "r"(sel));
    return d;
}
__device__ __forceinline__ void cp_async16(uint32_t smem_addr, const void* gptr) {
    asm volatile("cp.async.cg.shared.global [%0], [%1], 16;"
                 :: "r"(smem_addr), "l"(gptr) : "memory");
}
__device__ __forceinline__ void cp_async_wait_all() {
    asm volatile("cp.async.commit_group;" ::: "memory");
    asm volatile("cp.async.wait_group 0;" ::: "memory");
}
__device__ __forceinline__ void ldsm4(uint32_t* r, uint32_t addr) {
    asm volatile("ldmatrix.sync.aligned.m8n8.x4.shared.b16 {%0,%1,%2,%3}, [%4];"
                 : "=r"(r[0]), "=r"(r[1]), "=r"(r[2]), "=r"(r[3]) : "r"(addr));
}
__device__ __forceinline__ void ldsm4t(uint32_t* r, uint32_t addr) {
    asm volatile("ldmatrix.sync.aligned.m8n8.x4.trans.shared.b16 {%0,%1,%2,%3}, [%4];"
                 : "=r"(r[0]), "=r"(r[1]), "=r"(r[2]), "=r"(r[3]) : "r"(addr));
}
__device__ __forceinline__ void mma_f16(float* c, const uint32_t* a,
                                        const uint32_t* b) {
    asm volatile(
        "mma.sync.aligned.m16n8k16.row.col.f32.f16.f16.f32 "
        "{%0,%1,%2,%3}, {%4,%5,%6,%7}, {%8,%9}, {%0,%1,%2,%3};"
        : "+f"(c[0]), "+f"(c[1]), "+f"(c[2]), "+f"(c[3])
        : "r"(a[0]), "r"(a[1]), "r"(a[2]), "r"(a[3]), "r"(b[0]), "r"(b[1]));
}
// fp32 -> packed {fp16 hi << 16 | fp16 residual lo}
__device__ __forceinline__ uint32_t pack_split16(float v) {
    __half h = __float2half_rn(v);
    float hf = __half2float(h);
    __half l = __float2half_rn(v - hf);
    return ((uint32_t)__half_as_ushort(h) << 16) | __half_as_ushort(l);
}

// ---------------------------------------------------------------------------
// Kernel 1: proj = emb @ Qdense -> g_proj fp32 + g_pf16. (validated)
// ---------------------------------------------------------------------------
__global__ void __launch_bounds__(256) proj_kernel(const float* __restrict__ emb,
                                                   const float* __restrict__ Wq) {
    __shared__ float As[16 * 65];
    __shared__ float Bs[64 * 36];
    const int r0 = blockIdx.x * 16, c0 = blockIdx.y * 32;
    const int t = threadIdx.x;
    const int r = t & 15, cg = t >> 4;
    float2 acc = make_float2(0.f, 0.f);

    for (int kc = 0; kc < kD; kc += 64) {
        __syncthreads();
        {
            int ar = t >> 4, ak4 = t & 15;
            float4 v = make_float4(0.f, 0.f, 0.f, 0.f);
            if (r0 + ar < kV) v = *(const float4*)(emb + (r0 + ar) * kD + kc + ak4 * 4);
            float* d = As + ar * 65 + ak4 * 4;
            d[0] = v.x; d[1] = v.y; d[2] = v.z; d[3] = v.w;
        }
        {
            int c4 = t & 7;
#pragma unroll
            for (int j = 0; j < 2; j++) {
                int bk = (t >> 3) + 32 * j;
                float4 v = *(const float4*)(Wq + (kc + bk) * kD + c0 + c4 * 4);
                *(float4*)(Bs + bk * 36 + c4 * 4) = v;
            }
        }
        __syncthreads();
#pragma unroll 8
        for (int kk = 0; kk < 64; kk++) {
            float a = As[r * 65 + kk];
            float2 bv = *(const float2*)(Bs + kk * 36 + cg * 2);
            acc.x = fmaf(a, bv.x, acc.x);
            acc.y = fmaf(a, bv.y, acc.y);
        }
    }
    if (r0 + r < kV) {
        int idx = (r0 + r) * kD + c0 + cg * 2;
        *(float2*)(g_proj + idx) = acc;
        *(__half2*)(g_pf16 + idx) = __floats2half2_rn(acc.x, acc.y);
    }
}

// ---------------------------------------------------------------------------
// Kernel 2: G = proj projT -> packed fp16-split g_grams, col 0 zeroed.
// ---------------------------------------------------------------------------
__global__ void __launch_bounds__(256) gram_kernel() {
    __shared__ float As[32 * 130];
    __shared__ float Bs[32 * 130];
    const int i0 = blockIdx.x * 32, j0 = blockIdx.y * 32;
    const int t = threadIdx.x;
    const int tx = t & 15, ty = t >> 4;
    float a00 = 0.f, a01 = 0.f, a10 = 0.f, a11 = 0.f;

    for (int kc = 0; kc < kD; kc += 128) {
        __syncthreads();
        {
            int sr = t >> 3;
#pragma unroll
            for (int j = 0; j < 4; j++) {
                int c4 = (t & 7) + 8 * j;
                float4 va = make_float4(0.f, 0.f, 0.f, 0.f);
                float4 vb = make_float4(0.f, 0.f, 0.f, 0.f);
                if (i0 + sr < kV) va = *(const float4*)(g_proj + (i0 + sr) * kD + kc + c4 * 4);
                if (j0 + sr < kV) vb = *(const float4*)(g_proj + (j0 + sr) * kD + kc + c4 * 4);
                float2* da = (float2*)(As + sr * 130 + c4 * 4);
                float2* db = (float2*)(Bs + sr * 130 + c4 * 4);
                da[0] = make_float2(va.x, va.y); da[1] = make_float2(va.z, va.w);
                db[0] = make_float2(vb.x, vb.y); db[1] = make_float2(vb.z, vb.w);
            }
        }
        __syncthreads();
#pragma unroll 8
        for (int kk = 0; kk < 128; kk += 2) {
            float2 x0 = *(const float2*)(As + ty * 130 + kk);
            float2 x1 = *(const float2*)(As + (ty + 16) * 130 + kk);
            float2 y0 = *(const float2*)(Bs + tx * 130 + kk);
            float2 y1 = *(const float2*)(Bs + (tx + 16) * 130 + kk);
            a00 = fmaf(x0.x, y0.x, a00); a00 = fmaf(x0.y, y0.y, a00);
            a01 = fmaf(x0.x, y1.x, a01); a01 = fmaf(x0.y, y1.y, a01);
            a10 = fmaf(x1.x, y0.x, a10); a10 = fmaf(x1.y, y0.y, a10);
            a11 = fmaf(x1.x, y1.x, a11); a11 = fmaf(x1.y, y1.y, a11);
        }
    }
    int i = i0 + ty, j = j0 + tx;
    if (i < kV) {
        if (j < kV)      g_grams[i * kVP + j]      = j ? pack_split16(a00) : 0u;
        if (j + 16 < kV) g_grams[i * kVP + j + 16] = pack_split16(a01);
    }
    if (i + 16 < kV) {
        if (j < kV)      g_grams[(i + 16) * kVP + j]      = j ? pack_split16(a10) : 0u;
        if (j + 16 < kV) g_grams[(i + 16) * kVP + j + 16] = pack_split16(a11);
    }
}

// ---------------------------------------------------------------------------
// Kernel 3 (sbuild): grid (1024, 2); CTA = (batch, 32-q-row half).
// ---------------------------------------------------------------------------
__global__ void __launch_bounds__(256) sbuild_kernel(const int* __restrict__ ids_fr) {
    extern __shared__ char smem[];
    int* tfr = (int*)(smem + SB_TFR);
    const int b = blockIdx.x;
    const int h = blockIdx.y;
    const int tid = threadIdx.x;

    if (tid < 64) tfr[tid] = ids_fr[b * 64 + tid];
    __syncthreads();

    for (int idx = tid; idx < 32 * 76; idx += 256) {
        int r = idx / 76, c = idx - r * 76;
        ((uint4*)(smem + r * GSTRB))[c] =
            __ldg((const uint4*)(g_grams + (size_t)tfr[32 * h + r] * kVP) + c);
    }
    __syncthreads();

    uint32_t* sp = g_sp + ((size_t)b << 12);
    for (int t4 = tid; t4 < 1024; t4 += 256) {
        int i = t4 >> 5, kp = t4 & 31;
        int q = 32 * h + i;
        const uint32_t* grow = (const uint32_t*)(smem + i * GSTRB);
        uint32_t v0 = grow[tfr[2 * kp]];
        uint32_t v1 = grow[tfr[2 * kp + 1]];
        sp[(q << 5) + kp]        = prmt(v0, v1, 0x7632);   // hi plane
        sp[2048 + (q << 5) + kp] = prmt(v0, v1, 0x5410);   // lo plane
    }
}

// ---------------------------------------------------------------------------
// Kernel 4 (main): grid (1024, 4); CTA = (batch, 128-col quarter), 128 thr,
// 36.4 KB smem, 4 CTAs/SM. Warp tile 32q x 64n. Staging via cp.async.
// Direct epilogue (r14-validated).
// ---------------------------------------------------------------------------
__global__ void __launch_bounds__(128, 4) main_kernel(
    const int* __restrict__ ids_en, const int* __restrict__ ids_fr,
    const float* __restrict__ emb, float* __restrict__ out) {
    extern __shared__ char smem[];
    const uint32_t sb = smem_u32(smem);
    int* tfr = (int*)(smem + OFF_TFR);
    int* ten = (int*)(smem + OFF_TEN);

    const int b = blockIdx.x;
    const int coff = blockIdx.y * kN;
    const int tid = threadIdx.x;
    const int lane = tid & 31, w = tid >> 5;

    if (tid < 64) {
        tfr[tid] = ids_fr[b * 64 + tid];
        ten[tid] = ids_en[b * 64 + tid];
    }
    __syncthreads();

    // ---- Stage S planes via cp.async (pure copy; 8 x 16B per thread) --------
    {
        const uint4* sp = (const uint4*)(g_sp + ((size_t)b << 12));
#pragma unroll
        for (int i = 0; i < 8; i++) {
            int idx = tid + 128 * i;
            int w4 = idx * 4;
            int p = w4 >> 11, rem = w4 & 2047;
            int q = rem >> 5, k0 = rem & 31;
            cp_async16(sb + (p ? OFF_SLO : OFF_SHI) + q * SROWB + k0 * 4, sp + idx);
        }
    }
    // ---- Stage V_hi plane via cp.async (pure copy; 8 x 16B per thread) ------
#pragma unroll
    for (int i = 0; i < 8; i++) {
        int idx = tid + 128 * i;
        int r = idx >> 4, g = idx & 15;
        cp_async16(sb + OFF_P + r * PROW2 + g * 16,
                   (const uint4*)(g_pf16 + (size_t)tfr[r] * kD + coff) + g);
    }
    cp_async_wait_all();
    __syncthreads();

    // ---- MMA: warp tile 32q x 64n (warps: mw = w&1, nw = w>>1) -------------
    const int mw = w & 1, nw = w >> 1;
    const uint32_t aS = sb + OFF_SHI
        + (uint32_t)(32 * mw + (lane & 15)) * SROWB + ((lane >> 4) * 16);
    const uint32_t bT = sb + OFF_P + (uint32_t)(lane & 15) * PROW2
        + (uint32_t)(64 * nw + (lane >> 4) * 8) * 2;

    float acc[2][8][4];
#pragma unroll
    for (int m = 0; m < 2; m++)
#pragma unroll
        for (int nt = 0; nt < 8; nt++)
#pragma unroll
            for (int i = 0; i < 4; i++) acc[m][nt][i] = 0.f;

#pragma unroll
    for (int ks = 0; ks < 4; ks++) {
        uint32_t AH0[4], AH1[4], AL0[4], AL1[4];
        ldsm4(AH0, aS + ks * 32);
        ldsm4(AH1, aS + 16 * SROWB + ks * 32);
        ldsm4(AL0, aS + DSL + ks * 32);
        ldsm4(AL1, aS + DSL + 16 * SROWB + ks * 32);
        uint32_t adr = bT + (uint32_t)(ks * 16) * PROW2;
#pragma unroll
        for (int j = 0; j < 2; j++) {
            uint32_t bH0[4], bH1[4];
            ldsm4t(bH0, adr + j * 64);
            ldsm4t(bH1, adr + j * 64 + 32);
            float* a0 = acc[0][4 * j];
            float* a1 = acc[1][4 * j];
            mma_f16(a0,      AH0, bH0);     mma_f16(a0,      AL0, bH0);
            mma_f16(a0 + 4,  AH0, bH0 + 2); mma_f16(a0 + 4,  AL0, bH0 + 2);
            mma_f16(a0 + 8,  AH0, bH1);     mma_f16(a0 + 8,  AL0, bH1);
            mma_f16(a0 + 12, AH0, bH1 + 2); mma_f16(a0 + 12, AL0, bH1 + 2);
            mma_f16(a1,      AH1, bH0);     mma_f16(a1,      AL1, bH0);
            mma_f16(a1 + 4,  AH1, bH0 + 2); mma_f16(a1 + 4,  AL1, bH0 + 2);
            mma_f16(a1 + 8,  AH1, bH1);     mma_f16(a1 + 8,  AL1, bH1);
            mma_f16(a1 + 12, AH1, bH1 + 2); mma_f16(a1 + 12, AL1, bH1 + 2);
        }
    }

    // ---- Epilogue (direct, r14-validated): out = enc + emb[ids_en] ----------
    const int cb = coff + 64 * nw + 2 * (lane & 3);
#pragma unroll
    for (int m = 0; m < 2; m++) {
        int ra = 32 * mw + 16 * m + (lane >> 2), rb = ra + 8;
        const float* ea = emb + (size_t)ten[ra] * kD + cb;
        const float* eb = emb + (size_t)ten[rb] * kD + cb;
        float* oa = out + ((size_t)b * 64 + ra) * kD + cb;
        float* ob = out + ((size_t)b * 64 + rb) * kD + cb;
#pragma unroll
        for (int nt = 0; nt < 8; nt++) {
            float2 ga = __ldg((const float2*)(ea + nt * 8));
            float2 gb = __ldg((const float2*)(eb + nt * 8));
            *(float2*)(oa + nt * 8) =
                make_float2(acc[m][nt][0] + ga.x, acc[m][nt][1] + ga.y);
            *(float2*)(ob + nt * 8) =
                make_float2(acc[m][nt][2] + gb.x, acc[m][nt][3] + gb.y);
        }
    }
}

// ---------------------------------------------------------------------------
extern "C" void kernel_launch(void* const* d_in, const int* in_sizes, int n_in,
                              void* d_out, int out_size) {
    (void)in_sizes; (void)n_in; (void)out_size;
    const int* ids_en = (const int*)d_in[0];
    const int* ids_fr = (const int*)d_in[1];
    const float* emb  = (const float*)d_in[2];
    const float* Wq   = (const float*)d_in[3];
    float* out        = (float*)d_out;

    proj_kernel<<<dim3(19, 16), 256>>>(emb, Wq);
    gram_kernel<<<dim3(10, 10), 256>>>();
    cudaFuncSetAttribute(sbuild_kernel, cudaFuncAttributeMaxDynamicSharedMemorySize,
                         SMEM_SB);
    sbuild_kernel<<<dim3(kB, 2), 256, SMEM_SB>>>(ids_fr);
    cudaFuncSetAttribute(main_kernel, cudaFuncAttributeMaxDynamicSharedMemorySize,
                         SMEM_MAIN);
    main_kernel<<<dim3(kB, 4), 128, SMEM_MAIN>>>(ids_en, ids_fr, emb, out);
}

// round 17
// speedup vs baseline: 1.4622x; 1.0251x over previous
#include <cuda_runtime.h>
#include <cuda_fp16.h>
#include <cstdint>

// ---------------------------------------------------------------------------
// out = emb[ids_en] + S @ V,  vocab collapse:
//   proj = emb @ Qdense [300,512] -> fp32 g_proj + fp16 g_pf16
//   G = proj projT -> packed fp16 {hi|lo} g_grams (stride 304, col 0 zeroed)
//   sbuild (per batch x 2 CTAs): gather 32 G rows coalesced, column-select ->
//     S hi/lo fp16 planes in global g_sp (L2-resident)
//   main (per 2-batch x 4 column-CTAs, 128 thr, 3 CTAs/SM): DOUBLE-BUFFERED
//     cp.async pipeline across the two batches -- batch 1's staging streams
//     in behind batch 0's MMA+epilogue. enc = S @ V via fp16 2-product mma
//     D = (S_hi + S_lo) * V_hi (32q x 64n warp tiles); out = enc + emb.
// (tcgen05 unavailable: harness builds through plain compute_103 PTX.)
// ---------------------------------------------------------------------------

namespace {
constexpr int kB = 1024;
constexpr int kV = 300;
constexpr int kVP = 304;      // g_grams row stride (words)
constexpr int kD = 512;
constexpr int kN = 128;       // cols per main CTA (batch split in 4)

// sbuild smem (32 G rows per CTA)
constexpr int GSTRB = 1216;                      // G row bytes (304 words)
constexpr int SB_TFR = 32 * GSTRB;               // 38,912
constexpr int SMEM_SB = SB_TFR + 256;            // 39,168 -> 5 CTAs/SM

// main smem: TWO buffers (double-buffered batch pipeline)
constexpr int PROW2 = 272;                       // P plane row stride (128 fp16 + 16B)
constexpr int SROWB = 144;                       // S plane row stride (64 fp16 + 16B)
constexpr int OFF_P   = 0;                       // V_hi plane
constexpr int OFF_SHI = 64 * PROW2;              // 17,408
constexpr int OFF_SLO = OFF_SHI + 64 * SROWB;    // 26,624
constexpr int DSL     = OFF_SLO - OFF_SHI;
constexpr int OFF_TFR = OFF_SLO + 64 * SROWB;    // 35,840
constexpr int OFF_TEN = OFF_TFR + 256;           // 36,096
constexpr int BUF     = OFF_TEN + 256;           // 36,352 per buffer
constexpr int SMEM_MAIN = 2 * BUF;               // 72,704 -> 3 CTAs/SM (218 KB)
}

__device__ float    g_proj [kV * kD];        // fp32 proj (gram input)
__device__ __half   g_pf16 [kV * kD];        // fp16 proj (main B operand)
__device__ uint32_t g_grams[kV * kVP];       // packed {fp16 hi | fp16 lo}, col 0 = 0
__device__ uint32_t g_sp   [kB * 4096];      // per-batch S planes: [b][2][64][32]

// ---------------- helpers --------------------------------------------------
__device__ __forceinline__ uint32_t smem_u32(const void* p) {
    uint32_t a;
    asm("{ .reg .u64 t; cvta.to.shared.u64 t, %1; cvt.u32.u64 %0, t; }"
        : "=r"(a) : "l"(p));
    return a;
}
__device__ __forceinline__ uint32_t prmt(uint32_t a, uint32_t b, uint32_t sel) {
    uint32_t d;
    asm("prmt.b32 %0, %1, %2, %3;" : "=r"(d) : "r"(a), "r"(b), "r"(sel));
    return d;
}
__device__ __forceinline__ void cp_async16(uint32_t smem_addr, const void* gptr) {
    asm volatile("cp.async.cg.shared.global [%0], [%1], 16;"
                 :: "r"(smem_addr), "l"(gptr) : "memory");
}
__device__ __forceinline__ void ldsm4(uint32_t* r, uint32_t addr) {
    asm volatile("ldmatrix.sync.aligned.m8n8.x4.shared.b16 {%0,%1,%2,%3}, [%4];"
                 : "=r"(r[0]), "=r"(r[1]), "=r"(r[2]), "=r"(r[3]) : "r"(addr));
}
__device__ __forceinline__ void ldsm4t(uint32_t* r, uint32_t addr) {
    asm volatile("ldmatrix.sync.aligned.m8n8.x4.trans.shared.b16 {%0,%1,%2,%3}, [%4];"
                 : "=r"(r[0]), "=r"(r[1]), "=r"(r[2]), "=r"(r[3]) : "r"(addr));
}
__device__ __forceinline__ void mma_f16(float* c, const uint32_t* a,
                                        const uint32_t* b) {
    asm volatile(
        "mma.sync.aligned.m16n8k16.row.col.f32.f16.f16.f32 "
        "{%0,%1,%2,%3}, {%4,%5,%6,%7}, {%8,%9}, {%0,%1,%2,%3};"
        : "+f"(c[0]), "+f"(c[1]), "+f"(c[2]), "+f"(c[3])
        : "r"(a[0]), "r"(a[1]), "r"(a[2]), "r"(a[3]), "r"(b[0]), "r"(b[1]));
}
// fp32 -> packed {fp16 hi << 16 | fp16 residual lo}
__device__ __forceinline__ uint32_t pack_split16(float v) {
    __half h = __float2half_rn(v);
    float hf = __half2float(h);
    __half l = __float2half_rn(v - hf);
    return ((uint32_t)__half_as_ushort(h) << 16) | __half_as_ushort(l);
}

// ---------------------------------------------------------------------------
// Kernel 1: proj = emb @ Qdense -> g_proj fp32 + g_pf16. (validated)
// ---------------------------------------------------------------------------
__global__ void __launch_bounds__(256) proj_kernel(const float* __restrict__ emb,
                                                   const float* __restrict__ Wq) {
    __shared__ float As[16 * 65];
    __shared__ float Bs[64 * 36];
    const int r0 = blockIdx.x * 16, c0 = blockIdx.y * 32;
    const int t = threadIdx.x;
    const int r = t & 15, cg = t >> 4;
    float2 acc = make_float2(0.f, 0.f);

    for (int kc = 0; kc < kD; kc += 64) {
        __syncthreads();
        {
            int ar = t >> 4, ak4 = t & 15;
            float4 v = make_float4(0.f, 0.f, 0.f, 0.f);
            if (r0 + ar < kV) v = *(const float4*)(emb + (r0 + ar) * kD + kc + ak4 * 4);
            float* d = As + ar * 65 + ak4 * 4;
            d[0] = v.x; d[1] = v.y; d[2] = v.z; d[3] = v.w;
        }
        {
            int c4 = t & 7;
#pragma unroll
            for (int j = 0; j < 2; j++) {
                int bk = (t >> 3) + 32 * j;
                float4 v = *(const float4*)(Wq + (kc + bk) * kD + c0 + c4 * 4);
                *(float4*)(Bs + bk * 36 + c4 * 4) = v;
            }
        }
        __syncthreads();
#pragma unroll 8
        for (int kk = 0; kk < 64; kk++) {
            float a = As[r * 65 + kk];
            float2 bv = *(const float2*)(Bs + kk * 36 + cg * 2);
            acc.x = fmaf(a, bv.x, acc.x);
            acc.y = fmaf(a, bv.y, acc.y);
        }
    }
    if (r0 + r < kV) {
        int idx = (r0 + r) * kD + c0 + cg * 2;
        *(float2*)(g_proj + idx) = acc;
        *(__half2*)(g_pf16 + idx) = __floats2half2_rn(acc.x, acc.y);
    }
}

// ---------------------------------------------------------------------------
// Kernel 2: G = proj projT -> packed fp16-split g_grams, col 0 zeroed.
// ---------------------------------------------------------------------------
__global__ void __launch_bounds__(256) gram_kernel() {
    __shared__ float As[32 * 130];
    __shared__ float Bs[32 * 130];
    const int i0 = blockIdx.x * 32, j0 = blockIdx.y * 32;
    const int t = threadIdx.x;
    const int tx = t & 15, ty = t >> 4;
    float a00 = 0.f, a01 = 0.f, a10 = 0.f, a11 = 0.f;

    for (int kc = 0; kc < kD; kc += 128) {
        __syncthreads();
        {
            int sr = t >> 3;
#pragma unroll
            for (int j = 0; j < 4; j++) {
                int c4 = (t & 7) + 8 * j;
                float4 va = make_float4(0.f, 0.f, 0.f, 0.f);
                float4 vb = make_float4(0.f, 0.f, 0.f, 0.f);
                if (i0 + sr < kV) va = *(const float4*)(g_proj + (i0 + sr) * kD + kc + c4 * 4);
                if (j0 + sr < kV) vb = *(const float4*)(g_proj + (j0 + sr) * kD + kc + c4 * 4);
                float2* da = (float2*)(As + sr * 130 + c4 * 4);
                float2* db = (float2*)(Bs + sr * 130 + c4 * 4);
                da[0] = make_float2(va.x, va.y); da[1] = make_float2(va.z, va.w);
                db[0] = make_float2(vb.x, vb.y); db[1] = make_float2(vb.z, vb.w);
            }
        }
        __syncthreads();
#pragma unroll 8
        for (int kk = 0; kk < 128; kk += 2) {
            float2 x0 = *(const float2*)(As + ty * 130 + kk);
            float2 x1 = *(const float2*)(As + (ty + 16) * 130 + kk);
            float2 y0 = *(const float2*)(Bs + tx * 130 + kk);
            float2 y1 = *(const float2*)(Bs + (tx + 16) * 130 + kk);
            a00 = fmaf(x0.x, y0.x, a00); a00 = fmaf(x0.y, y0.y, a00);
            a01 = fmaf(x0.x, y1.x, a01); a01 = fmaf(x0.y, y1.y, a01);
            a10 = fmaf(x1.x, y0.x, a10); a10 = fmaf(x1.y, y0.y, a10);
            a11 = fmaf(x1.x, y1.x, a11); a11 = fmaf(x1.y, y1.y, a11);
        }
    }
    int i = i0 + ty, j = j0 + tx;
    if (i < kV) {
        if (j < kV)      g_grams[i * kVP + j]      = j ? pack_split16(a00) : 0u;
        if (j + 16 < kV) g_grams[i * kVP + j + 16] = pack_split16(a01);
    }
    if (i + 16 < kV) {
        if (j < kV)      g_grams[(i + 16) * kVP + j]      = j ? pack_split16(a10) : 0u;
        if (j + 16 < kV) g_grams[(i + 16) * kVP + j + 16] = pack_split16(a11);
    }
}

// ---------------------------------------------------------------------------
// Kernel 3 (sbuild): grid (1024, 2); CTA = (batch, 32-q-row half).
// ---------------------------------------------------------------------------
__global__ void __launch_bounds__(256) sbuild_kernel(const int* __restrict__ ids_fr) {
    extern __shared__ char smem[];
    int* tfr = (int*)(smem + SB_TFR);
    const int b = blockIdx.x;
    const int h = blockIdx.y;
    const int tid = threadIdx.x;

    if (tid < 64) tfr[tid] = ids_fr[b * 64 + tid];
    __syncthreads();

    for (int idx = tid; idx < 32 * 76; idx += 256) {
        int r = idx / 76, c = idx - r * 76;
        ((uint4*)(smem + r * GSTRB))[c] =
            __ldg((const uint4*)(g_grams + (size_t)tfr[32 * h + r] * kVP) + c);
    }
    __syncthreads();

    uint32_t* sp = g_sp + ((size_t)b << 12);
    for (int t4 = tid; t4 < 1024; t4 += 256) {
        int i = t4 >> 5, kp = t4 & 31;
        int q = 32 * h + i;
        const uint32_t* grow = (const uint32_t*)(smem + i * GSTRB);
        uint32_t v0 = grow[tfr[2 * kp]];
        uint32_t v1 = grow[tfr[2 * kp + 1]];
        sp[(q << 5) + kp]        = prmt(v0, v1, 0x7632);   // hi plane
        sp[2048 + (q << 5) + kp] = prmt(v0, v1, 0x5410);   // lo plane
    }
}

// ---------------------------------------------------------------------------
// Kernel 4 (main): grid (512, 4); CTA = (batch-pair, 128-col quarter),
// 128 thr, 72.7 KB smem, 3 CTAs/SM. Double-buffered cp.async pipeline:
// batch b0+1's staging overlaps batch b0's MMA + epilogue.
// ---------------------------------------------------------------------------
__global__ void __launch_bounds__(128, 3) main_kernel(
    const int* __restrict__ ids_en, const int* __restrict__ ids_fr,
    const float* __restrict__ emb, float* __restrict__ out) {
    extern __shared__ char smem[];
    const uint32_t sb = smem_u32(smem);

    const int b0 = blockIdx.x * 2;
    const int coff = blockIdx.y * kN;
    const int tid = threadIdx.x;
    const int lane = tid & 31, w = tid >> 5;

    // ---- Load token ids for BOTH batches -----------------------------------
    if (tid < 64) {
#pragma unroll
        for (int ib = 0; ib < 2; ib++) {
            ((int*)(smem + ib * BUF + OFF_TFR))[tid] = ids_fr[(b0 + ib) * 64 + tid];
            ((int*)(smem + ib * BUF + OFF_TEN))[tid] = ids_en[(b0 + ib) * 64 + tid];
        }
    }
    __syncthreads();

    // ---- Prefetch both buffers (two cp.async commit groups) ----------------
#pragma unroll
    for (int ib = 0; ib < 2; ib++) {
        const uint32_t bb = sb + ib * BUF;
        const int* tfr = (const int*)(smem + ib * BUF + OFF_TFR);
        const uint4* sp = (const uint4*)(g_sp + ((size_t)(b0 + ib) << 12));
#pragma unroll
        for (int i = 0; i < 8; i++) {          // S planes (pure copy)
            int idx = tid + 128 * i;
            int w4 = idx * 4;
            int p = w4 >> 11, rem = w4 & 2047;
            int q = rem >> 5, k0 = rem & 31;
            cp_async16(bb + (p ? OFF_SLO : OFF_SHI) + q * SROWB + k0 * 4, sp + idx);
        }
#pragma unroll
        for (int i = 0; i < 8; i++) {          // V_hi plane (gathered rows)
            int idx = tid + 128 * i;
            int r = idx >> 4, g = idx & 15;
            cp_async16(bb + OFF_P + r * PROW2 + g * 16,
                       (const uint4*)(g_pf16 + (size_t)tfr[r] * kD + coff) + g);
        }
        asm volatile("cp.async.commit_group;" ::: "memory");
    }
    asm volatile("cp.async.wait_group 1;" ::: "memory");   // buffer 0 ready
    __syncthreads();

    const int mw = w & 1, nw = w >> 1;

    // ---- Process both batches; buffer 1 streams in behind batch 0 ----------
#pragma unroll
    for (int ib = 0; ib < 2; ib++) {
        if (ib == 1) {
            asm volatile("cp.async.wait_group 0;" ::: "memory");
            __syncthreads();
        }
        const uint32_t bb = sb + ib * BUF;
        const int* ten = (const int*)(smem + ib * BUF + OFF_TEN);
        const int b = b0 + ib;

        const uint32_t aS = bb + OFF_SHI
            + (uint32_t)(32 * mw + (lane & 15)) * SROWB + ((lane >> 4) * 16);
        const uint32_t bT = bb + OFF_P + (uint32_t)(lane & 15) * PROW2
            + (uint32_t)(64 * nw + (lane >> 4) * 8) * 2;

        float acc[2][8][4];
#pragma unroll
        for (int m = 0; m < 2; m++)
#pragma unroll
            for (int nt = 0; nt < 8; nt++)
#pragma unroll
                for (int i = 0; i < 4; i++) acc[m][nt][i] = 0.f;

#pragma unroll
        for (int ks = 0; ks < 4; ks++) {
            uint32_t AH0[4], AH1[4], AL0[4], AL1[4];
            ldsm4(AH0, aS + ks * 32);
            ldsm4(AH1, aS + 16 * SROWB + ks * 32);
            ldsm4(AL0, aS + DSL + ks * 32);
            ldsm4(AL1, aS + DSL + 16 * SROWB + ks * 32);
            uint32_t adr = bT + (uint32_t)(ks * 16) * PROW2;
#pragma unroll
            for (int j = 0; j < 2; j++) {
                uint32_t bH0[4], bH1[4];
                ldsm4t(bH0, adr + j * 64);
                ldsm4t(bH1, adr + j * 64 + 32);
                float* a0 = acc[0][4 * j];
                float* a1 = acc[1][4 * j];
                mma_f16(a0,      AH0, bH0);     mma_f16(a0,      AL0, bH0);
                mma_f16(a0 + 4,  AH0, bH0 + 2); mma_f16(a0 + 4,  AL0, bH0 + 2);
                mma_f16(a0 + 8,  AH0, bH1);     mma_f16(a0 + 8,  AL0, bH1);
                mma_f16(a0 + 12, AH0, bH1 + 2); mma_f16(a0 + 12, AL0, bH1 + 2);
                mma_f16(a1,      AH1, bH0);     mma_f16(a1,      AL1, bH0);
                mma_f16(a1 + 4,  AH1, bH0 + 2); mma_f16(a1 + 4,  AL1, bH0 + 2);
                mma_f16(a1 + 8,  AH1, bH1);     mma_f16(a1 + 8,  AL1, bH1);
                mma_f16(a1 + 12, AH1, bH1 + 2); mma_f16(a1 + 12, AL1, bH1 + 2);
            }
        }

        // ---- Epilogue (direct, validated): out = enc + emb[ids_en] ----------
        const int cb = coff + 64 * nw + 2 * (lane & 3);
#pragma unroll
        for (int m = 0; m < 2; m++) {
            int ra = 32 * mw + 16 * m + (lane >> 2), rb = ra + 8;
            const float* ea = emb + (size_t)ten[ra] * kD + cb;
            const float* eb = emb + (size_t)ten[rb] * kD + cb;
            float* oa = out + ((size_t)b * 64 + ra) * kD + cb;
            float* ob = out + ((size_t)b * 64 + rb) * kD + cb;
#pragma unroll
            for (int nt = 0; nt < 8; nt++) {
                float2 ga = __ldg((const float2*)(ea + nt * 8));
                float2 gb = __ldg((const float2*)(eb + nt * 8));
                *(float2*)(oa + nt * 8) =
                    make_float2(acc[m][nt][0] + ga.x, acc[m][nt][1] + ga.y);
                *(float2*)(ob + nt * 8) =
                    make_float2(acc[m][nt][2] + gb.x, acc[m][nt][3] + gb.y);
            }
        }
    }
}

// ---------------------------------------------------------------------------
extern "C" void kernel_launch(void* const* d_in, const int* in_sizes, int n_in,
                              void* d_out, int out_size) {
    (void)in_sizes; (void)n_in; (void)out_size;
    const int* ids_en = (const int*)d_in[0];
    const int* ids_fr = (const int*)d_in[1];
    const float* emb  = (const float*)d_in[2];
    const float* Wq   = (const float*)d_in[3];
    float* out        = (float*)d_out;

    proj_kernel<<<dim3(19, 16), 256>>>(emb, Wq);
    gram_kernel<<<dim3(10, 10), 256>>>();
    cudaFuncSetAttribute(sbuild_kernel, cudaFuncAttributeMaxDynamicSharedMemorySize,
                         SMEM_SB);
    sbuild_kernel<<<dim3(kB, 2), 256, SMEM_SB>>>(ids_fr);
    cudaFuncSetAttribute(main_kernel, cudaFuncAttributeMaxDynamicSharedMemorySize,
                         SMEM_MAIN);
    main_kernel<<<dim3(kB / 2, 4), 128, SMEM_MAIN>>>(ids_en, ids_fr, emb, out);
}